// round 5
// baseline (speedup 1.0000x reference)
#include <cuda_runtime.h>
#include <stdint.h>

// Problem shape (fixed by the reference): x is (T, B, 1) fp32, lr scalar.
#define T_DIM 8192
#define B_DIM 4096
#define B2    (B_DIM / 2)    // 2048 column-pairs
#define S_CHUNKS 128
#define CH 64                // T_DIM / S_CHUNKS
#define NW 2                 // CH / 32 words per column

// Scratch (device globals). All chunk-major, coalesced over columns.
__device__ float2 g_coef0[S_CHUNKS * B_DIM];  // (A0, C0) per (s,b)        4 MB
__device__ float2 g_coef1[S_CHUNKS * B_DIM];  // (A1, C1) per (s,b)        4 MB
__device__ uint2  g_bits [S_CHUNKS * B_DIM];  // 64 packed x bits          4 MB
__device__ float2 g_xprev[S_CHUNKS * B2];     // x[t0-1] per (s,pair)      2 MB
__device__ float  g_st0  [S_CHUNKS * B_DIM];  // p0 entering chunk         2 MB
__device__ float  g_st1  [S_CHUNKS * B_DIM];  // p1 entering chunk         2 MB

__device__ __forceinline__ float clamp_lr(const float* lrp) {
    return fminf(fmaxf(*lrp, 0.0f), 1.0f);
}

// r^n, n in [0,127], square-and-multiply (no smem, no sync).
__device__ __forceinline__ float rpow_int(float r, int n) {
    float res = 1.0f, base = r;
    #pragma unroll
    for (int i = 0; i < 7; i++) {
        res  = ((n >> i) & 1) ? res * base : res;
        base = base * base;
    }
    return res;
}

// ---------------------------------------------------------------------------
// Pass 1: per (chunk s, column-pair). 262144 threads (same as R1/R4) but each
// LDG is 64-bit -> 2x bytes-in-flight per warp at the same register budget.
// Chunk multiplier A = r^(#updates) via POPCOUNT of the obs_prev bit stream;
// only the additive C term needs per-step FMA:
//   pb==0: C0 = C0*r + lr*x_t    pb==1: C1 = C1*r + lr*x_t
// ---------------------------------------------------------------------------
__global__ void __launch_bounds__(256) pass1_kernel(
    const float2* __restrict__ x2, const float* __restrict__ lrp)
{
    const int b2 = blockIdx.x * blockDim.x + threadIdx.x;   // [0, B2)
    const int s  = blockIdx.y;
    const float lr = clamp_lr(lrp);
    const float r  = 1.0f - lr;

    const float2* xp = x2 + (size_t)(s * CH) * B2 + b2;

    float2 xprev = make_float2(0.f, 0.f);
    if (s > 0) xprev = xp[-(ptrdiff_t)B2];
    g_xprev[s * B2 + b2] = xprev;

    bool  pb[2] = { xprev.x != 0.f, xprev.y != 0.f };
    float C0[2] = { 0.f, 0.f }, C1[2] = { 0.f, 0.f };
    uint32_t W[2][NW];

    #pragma unroll
    for (int h = 0; h < NW; h++) {
        uint32_t w0 = 0, w1 = 0;
        #pragma unroll
        for (int i0 = 0; i0 < 32; i0 += 8) {
            float2 xv[8];                                   // 8 x LDG.64 batch
            #pragma unroll
            for (int j = 0; j < 8; j++)
                xv[j] = xp[(size_t)(h * 32 + i0 + j) * B2];
            #pragma unroll
            for (int j = 0; j < 8; j++) {
                const uint32_t bit = 1u << (i0 + j);
                {   // column 0
                    const float v  = xv[j].x;
                    const bool  xb = (v != 0.0f);
                    const float t  = v * lr;                // exact: x in {0,1}
                    C0[0] = pb[0] ? C0[0] : fmaf(C0[0], r, t);
                    C1[0] = pb[0] ? fmaf(C1[0], r, t) : C1[0];
                    w0 = xb ? (w0 | bit) : w0;
                    pb[0] = xb;
                }
                {   // column 1
                    const float v  = xv[j].y;
                    const bool  xb = (v != 0.0f);
                    const float t  = v * lr;
                    C0[1] = pb[1] ? C0[1] : fmaf(C0[1], r, t);
                    C1[1] = pb[1] ? fmaf(C1[1], r, t) : C1[1];
                    w1 = xb ? (w1 | bit) : w1;
                    pb[1] = xb;
                }
            }
        }
        W[0][h] = w0;
        W[1][h] = w1;
    }

    const float xpv[2] = { xprev.x, xprev.y };
    #pragma unroll
    for (int c = 0; c < 2; c++) {
        // obs_prev stream over the chunk = [xprev, x_0 .. x_62]
        const int ones = __popc(W[c][0]) + __popc(W[c][1]);
        const int n1   = ones - (int)(W[c][1] >> 31) + (xpv[c] != 0.f ? 1 : 0);
        const int b    = 2 * b2 + c;
        g_coef0[s * B_DIM + b] = make_float2(rpow_int(r, CH - n1), C0[c]);
        g_coef1[s * B_DIM + b] = make_float2(rpow_int(r, n1),      C1[c]);
        g_bits [s * B_DIM + b] = make_uint2(W[c][0], W[c][1]);
    }
}

// ---------------------------------------------------------------------------
// Scan: p0/p1 lineages independent -> 8192 threads, 128 sequential affine
// compositions each (coef data largely L2-resident after pass1).
// ---------------------------------------------------------------------------
__global__ void __launch_bounds__(256) scan_kernel()
{
    const int tid = blockIdx.x * blockDim.x + threadIdx.x;   // [0, 2*B)
    const int b   = tid & (B_DIM - 1);
    const float2* coef = (tid < B_DIM) ? g_coef0 : g_coef1;
    float*        st   = (tid < B_DIM) ? g_st0   : g_st1;

    float p = 0.5f;
    #pragma unroll 16
    for (int s = 0; s < S_CHUNKS; s++) {
        const float2 c = coef[s * B_DIM + b];
        st[s * B_DIM + b] = p;
        p = fmaf(p, c.x, c.y);
    }
}

// ---------------------------------------------------------------------------
// Pass 2: replay each chunk from its entry state using the packed bits
// (x never re-read from HBM). 2 columns/thread, STG.64 per step.
// ---------------------------------------------------------------------------
__global__ void __launch_bounds__(256) pass2_kernel(
    float2* __restrict__ out2, const float* __restrict__ lrp)
{
    const int b2 = blockIdx.x * blockDim.x + threadIdx.x;
    const int s  = blockIdx.y;
    const float lr = clamp_lr(lrp);

    float2* op = out2 + (size_t)(s * CH) * B2 + b2;
    const int b = 2 * b2;

    float p0[2] = { g_st0[s * B_DIM + b], g_st0[s * B_DIM + b + 1] };
    float p1[2] = { g_st1[s * B_DIM + b], g_st1[s * B_DIM + b + 1] };
    const uint2 bw0 = g_bits[s * B_DIM + b];
    const uint2 bw1 = g_bits[s * B_DIM + b + 1];
    uint32_t W[2][NW] = { { bw0.x, bw0.y }, { bw1.x, bw1.y } };
    const float2 xprev = g_xprev[s * B2 + b2];
    bool pb[2] = { xprev.x != 0.f, xprev.y != 0.f };

    #pragma unroll
    for (int wi = 0; wi < NW; wi++) {
        #pragma unroll
        for (int i = 0; i < 32; i++) {
            float ov[2];
            #pragma unroll
            for (int c = 0; c < 2; c++) {
                const bool  xb = (W[c][wi] >> i) & 1u;
                const float xv = xb ? 1.0f : 0.0f;
                const float l0 = pb[c] ? 0.0f : lr;
                const float l1 = pb[c] ? lr   : 0.0f;
                p0[c] = fmaf(l0, xv - p0[c], p0[c]);
                p1[c] = fmaf(l1, xv - p1[c], p1[c]);
                ov[c] = xb ? p1[c] : p0[c];
                pb[c] = xb;
            }
            op[(size_t)(wi * 32 + i) * B2] = make_float2(ov[0], ov[1]);
        }
    }
}

extern "C" void kernel_launch(void* const* d_in, const int* in_sizes, int n_in,
                              void* d_out, int out_size)
{
    const float* x  = (const float*)d_in[0];
    const float* lr = (const float*)d_in[1];
    if (n_in >= 2 && in_sizes[0] == 1) { x = (const float*)d_in[1]; lr = (const float*)d_in[0]; }

    dim3 blk(256);
    dim3 grid_pass(B2 / 256, S_CHUNKS);   // (8, 128) = 1024 blocks, 262144 threads

    pass1_kernel<<<grid_pass, blk>>>((const float2*)x, lr);
    scan_kernel<<<(2 * B_DIM) / 256, blk>>>();
    pass2_kernel<<<grid_pass, blk>>>((float2*)d_out, lr);
}